// round 1
// baseline (speedup 1.0000x reference)
#include <cuda_runtime.h>
#include <cstdint>

// Problem constants (fixed shapes from setup_inputs)
#define BATCH   4
#define CIN     128
#define COUT    128
#define HDIM    128
#define WDIM    128
#define HW      (HDIM * WDIM)      // 16384
#define NGROUP  4
#define CG      32                 // CIN / NGROUP
#define KTAPS   9                  // 3x3
#define RTOT    (CIN * KTAPS)      // 1152 reduction rows
#define TPX     32                 // pixels per block

// Shared memory layout (floats):
//  samp [RTOT][TPX]            : 36864 floats
//  sw   [4][36*TPX]            :  4608 floats (bilinear corner weights per (g,k,px))
//  sidx [4][36*TPX] (int)      :  4608 ints   (clamped gather indices)
//  ss0[32], ss1[32], swo[144]
#define SMEM_FLOATS (RTOT*TPX + 4*1152 + 4*1152 + 32 + 32 + 144)
#define SMEM_BYTES  (SMEM_FLOATS * 4)   // 185152

// Transposed deform weights: wT[r][o], r = c*9 + k
__device__ float g_wT[RTOT * COUT];

__global__ void prep_wT_kernel(const float* __restrict__ wd) {
    int idx = blockIdx.x * 256 + threadIdx.x;
    if (idx < RTOT * COUT) {
        int r = idx >> 7;       // reduction row
        int o = idx & 127;      // output channel
        g_wT[idx] = wd[o * RTOT + r];   // wd is [O][C][3][3] flat = [O][1152]
    }
}

__global__ void __launch_bounds__(256, 1) deform_kernel(
    const float* __restrict__ x,        // [B,C,H,W]
    const float* __restrict__ shape,    // [B,2,H,W]
    const float* __restrict__ w_offset, // [72][2]
    float* __restrict__ out)            // [B,COUT,H,W]
{
    extern __shared__ float smem[];
    float* samp = smem;                         // [1152][32]
    float* sw   = samp + RTOT * TPX;            // [4][1152]
    int*   sidx = (int*)(sw + 4 * 1152);        // [4][1152]
    float* ss0  = (float*)(sidx + 4 * 1152);    // [32]
    float* ss1  = ss0 + 32;                     // [32]
    float* swo  = ss1 + 32;                     // [144]

    const int tid = threadIdx.x;
    // 512 pixel tiles per batch image: h in [0,128), w tile in [0,4)
    const int b   = blockIdx.x >> 9;
    const int rem = blockIdx.x & 511;
    const int h   = rem >> 2;
    const int w0  = (rem & 3) << 5;

    // ---- stage shape values + offset weights ----
    if (tid < 32)       ss0[tid]    = shape[(size_t)(b*2+0)*HW + h*WDIM + w0 + tid];
    else if (tid < 64)  ss1[tid-32] = shape[(size_t)(b*2+1)*HW + h*WDIM + w0 + (tid-32)];
    if (tid < 144)      swo[tid]    = w_offset[tid];
    __syncthreads();

    // ---- phase A1: bilinear params per (g,k,px) : 36*32 = 1152 items ----
    for (int i = tid; i < 36 * TPX; i += 256) {
        int gk = i >> 5, px = i & 31;       // gk = g*9 + k
        int k  = gk % 9;
        int ky = k / 3, kx = k % 3;
        float s0 = ss0[px], s1 = ss1[px];
        // offset channel for (gk, axis): ((gk)*2 + axis), w_offset row stride 2
        float offy = swo[gk*4 + 0] * s0 + swo[gk*4 + 1] * s1;
        float offx = swo[gk*4 + 2] * s0 + swo[gk*4 + 3] * s1;
        float py  = offy + (float)(ky - 1 + h);
        float pxf = offx + (float)(kx - 1 + w0 + px);
        float y0f = floorf(py), x0f = floorf(pxf);
        float fy = py - y0f, fx = pxf - x0f;
        int y0 = (int)y0f, x0 = (int)x0f;
        #pragma unroll
        for (int t = 0; t < 4; t++) {
            int dy = t >> 1, dx = t & 1;
            int yi = y0 + dy, xi = x0 + dx;
            bool valid = (yi >= 0) && (yi < HDIM) && (xi >= 0) && (xi < WDIM);
            float wy = dy ? fy : 1.0f - fy;
            float wx = dx ? fx : 1.0f - fx;
            int yc = min(max(yi, 0), HDIM - 1);
            int xc = min(max(xi, 0), WDIM - 1);
            sw  [t*1152 + i] = valid ? (wy * wx) : 0.0f;
            sidx[t*1152 + i] = yc * WDIM + xc;
        }
    }
    __syncthreads();

    // ---- phase A2: gather-sample im2col tile [1152 rows][32 px] ----
    for (int i = tid; i < 36 * TPX; i += 256) {
        int gk = i >> 5, px = i & 31;
        int g = gk / 9, k = gk - g * 9;
        float a0 = sw[0*1152 + i], a1 = sw[1*1152 + i];
        float a2 = sw[2*1152 + i], a3 = sw[3*1152 + i];
        int i0 = sidx[0*1152 + i], i1 = sidx[1*1152 + i];
        int i2 = sidx[2*1152 + i], i3 = sidx[3*1152 + i];
        const float* xb = x + ((size_t)b * CIN + g * CG) * HW;
        // row for cg=0 of this group/tap; +288 floats per cg (9 rows * 32 px)
        float* dst = samp + ((size_t)(g * CG) * KTAPS + k) * TPX + px;
        #pragma unroll 4
        for (int cg = 0; cg < CG; cg++) {
            const float* xc = xb + (size_t)cg * HW;
            dst[cg * (KTAPS * TPX)] = a0 * xc[i0] + a1 * xc[i1] + a2 * xc[i2] + a3 * xc[i3];
        }
    }
    __syncthreads();

    // ---- phase B: GEMM — thread = (o, 16 px) via packed f32x2 FMA ----
    const int o   = tid & 127;
    const int px0 = (tid >> 7) << 4;    // 0 or 16

    uint64_t acc[8];
    #pragma unroll
    for (int j = 0; j < 8; j++) acc[j] = 0ull;

    const float* wp = g_wT + o;
    #pragma unroll 4
    for (int r = 0; r < RTOT; r++) {
        float wv = wp[(size_t)r * 128];
        uint64_t wv2;
        asm("mov.b64 %0, {%1, %1};" : "=l"(wv2) : "r"(__float_as_uint(wv)));
        const ulonglong2* srow =
            reinterpret_cast<const ulonglong2*>(samp + (size_t)r * TPX + px0);
        #pragma unroll
        for (int j2 = 0; j2 < 4; j2++) {
            ulonglong2 p = srow[j2];   // LDS.128, warp-uniform address -> broadcast
            asm("fma.rn.f32x2 %0, %1, %2, %0;" : "+l"(acc[2*j2  ]) : "l"(p.x), "l"(wv2));
            asm("fma.rn.f32x2 %0, %1, %2, %0;" : "+l"(acc[2*j2+1]) : "l"(p.y), "l"(wv2));
        }
    }

    // ---- ReLU + store 16 consecutive floats ----
    float* op = out + ((size_t)b * COUT + o) * HW + h * WDIM + w0 + px0;
    #pragma unroll
    for (int j2 = 0; j2 < 4; j2++) {
        float4 v;
        v.x = fmaxf(__uint_as_float((uint32_t)(acc[2*j2  ]      )), 0.0f);
        v.y = fmaxf(__uint_as_float((uint32_t)(acc[2*j2  ] >> 32)), 0.0f);
        v.z = fmaxf(__uint_as_float((uint32_t)(acc[2*j2+1]      )), 0.0f);
        v.w = fmaxf(__uint_as_float((uint32_t)(acc[2*j2+1] >> 32)), 0.0f);
        reinterpret_cast<float4*>(op)[j2] = v;
    }
}

extern "C" void kernel_launch(void* const* d_in, const int* in_sizes, int n_in,
                              void* d_out, int out_size) {
    const float* x        = (const float*)d_in[0];
    const float* shape    = (const float*)d_in[1];
    const float* w_offset = (const float*)d_in[2];
    const float* w_deform = (const float*)d_in[3];
    float* out = (float*)d_out;

    cudaFuncSetAttribute(deform_kernel,
                         cudaFuncAttributeMaxDynamicSharedMemorySize, SMEM_BYTES);

    prep_wT_kernel<<<(RTOT * COUT + 255) / 256, 256>>>(w_deform);

    const int nblocks = BATCH * HDIM * (WDIM / TPX);   // 2048
    deform_kernel<<<nblocks, 256, SMEM_BYTES>>>(x, shape, w_offset, out);
}

// round 2
// speedup vs baseline: 1.0059x; 1.0059x over previous
#include <cuda_runtime.h>
#include <cstdint>

// Problem constants (fixed shapes from setup_inputs)
#define BATCH   4
#define CIN     128
#define COUT    128
#define HDIM    128
#define WDIM    128
#define HW      (HDIM * WDIM)      // 16384
#define NGROUP  4
#define CG      32                 // CIN / NGROUP
#define KTAPS   9                  // 3x3
#define RTOT    (CIN * KTAPS)      // 1152 reduction rows
#define TPX     32                 // pixels per block
#define NTHREADS 512

// Shared memory layout (floats):
//  samp [RTOT][TPX]            : 36864 floats
//  sw   [4][36*TPX]            :  4608 floats (bilinear corner weights per (g,k,px))
//  sidx [4][36*TPX] (int)      :  4608 ints   (clamped gather indices)
//  ss0[32], ss1[32], swo[144]
#define SMEM_FLOATS (RTOT*TPX + 4*1152 + 4*1152 + 32 + 32 + 144)
#define SMEM_BYTES  (SMEM_FLOATS * 4)   // 185152

// Transposed deform weights: wT[r][o], r = c*9 + k
__device__ float g_wT[RTOT * COUT];

__global__ void prep_wT_kernel(const float* __restrict__ wd) {
    int idx = blockIdx.x * 256 + threadIdx.x;
    if (idx < RTOT * COUT) {
        int r = idx >> 7;       // reduction row
        int o = idx & 127;      // output channel
        g_wT[idx] = wd[o * RTOT + r];   // wd is [O][C][3][3] flat = [O][1152]
    }
}

__global__ void __launch_bounds__(NTHREADS, 1) deform_kernel(
    const float* __restrict__ x,        // [B,C,H,W]
    const float* __restrict__ shape,    // [B,2,H,W]
    const float* __restrict__ w_offset, // [72][2]
    float* __restrict__ out)            // [B,COUT,H,W]
{
    extern __shared__ float smem[];
    float* samp = smem;                         // [1152][32]
    float* sw   = samp + RTOT * TPX;            // [4][1152]
    int*   sidx = (int*)(sw + 4 * 1152);        // [4][1152]
    float* ss0  = (float*)(sidx + 4 * 1152);    // [32]
    float* ss1  = ss0 + 32;                     // [32]
    float* swo  = ss1 + 32;                     // [144]

    const int tid = threadIdx.x;
    // 512 pixel tiles per batch image: h in [0,128), w tile in [0,4)
    const int b   = blockIdx.x >> 9;
    const int rem = blockIdx.x & 511;
    const int h   = rem >> 2;
    const int w0  = (rem & 3) << 5;

    // ---- stage shape values + offset weights ----
    if (tid < 32)       ss0[tid]    = shape[(size_t)(b*2+0)*HW + h*WDIM + w0 + tid];
    else if (tid < 64)  ss1[tid-32] = shape[(size_t)(b*2+1)*HW + h*WDIM + w0 + (tid-32)];
    if (tid < 144)      swo[tid]    = w_offset[tid];
    __syncthreads();

    // ---- phase A1: bilinear params per (g,k,px) : 36*32 = 1152 items ----
    for (int i = tid; i < 36 * TPX; i += NTHREADS) {
        int gk = i >> 5, px = i & 31;       // gk = g*9 + k
        int k  = gk % 9;
        int ky = k / 3, kx = k % 3;
        float s0 = ss0[px], s1 = ss1[px];
        // offset channel for (gk, axis): ((gk)*2 + axis), w_offset row stride 2
        float offy = swo[gk*4 + 0] * s0 + swo[gk*4 + 1] * s1;
        float offx = swo[gk*4 + 2] * s0 + swo[gk*4 + 3] * s1;
        float py  = offy + (float)(ky - 1 + h);
        float pxf = offx + (float)(kx - 1 + w0 + px);
        float y0f = floorf(py), x0f = floorf(pxf);
        float fy = py - y0f, fx = pxf - x0f;
        int y0 = (int)y0f, x0 = (int)x0f;
        #pragma unroll
        for (int t = 0; t < 4; t++) {
            int dy = t >> 1, dx = t & 1;
            int yi = y0 + dy, xi = x0 + dx;
            bool valid = (yi >= 0) && (yi < HDIM) && (xi >= 0) && (xi < WDIM);
            float wy = dy ? fy : 1.0f - fy;
            float wx = dx ? fx : 1.0f - fx;
            int yc = min(max(yi, 0), HDIM - 1);
            int xc = min(max(xi, 0), WDIM - 1);
            sw  [t*1152 + i] = valid ? (wy * wx) : 0.0f;
            sidx[t*1152 + i] = yc * WDIM + xc;
        }
    }
    __syncthreads();

    // ---- phase A2: gather-sample im2col tile [1152 rows][32 px] ----
    // item = (gk, px, cg-half): 36*32*2 = 2304 items, 16 cg each
    for (int i2 = tid; i2 < 36 * TPX * 2; i2 += NTHREADS) {
        int i  = i2 >> 1;            // (gk, px)
        int ch = i2 & 1;             // cg half: 0 -> cg 0..15, 1 -> cg 16..31
        int gk = i >> 5, px = i & 31;
        int g = gk / 9, k = gk - g * 9;
        float a0 = sw[0*1152 + i], a1 = sw[1*1152 + i];
        float a2 = sw[2*1152 + i], a3 = sw[3*1152 + i];
        int i0 = sidx[0*1152 + i], i1 = sidx[1*1152 + i];
        int i2d = sidx[2*1152 + i], i3 = sidx[3*1152 + i];
        const float* xb = x + ((size_t)b * CIN + g * CG + ch * 16) * HW;
        float* dst = samp + ((size_t)(g * CG + ch * 16) * KTAPS + k) * TPX + px;
        #pragma unroll 4
        for (int cg = 0; cg < 16; cg++) {
            const float* xc = xb + (size_t)cg * HW;
            dst[cg * (KTAPS * TPX)] = a0 * xc[i0] + a1 * xc[i1] + a2 * xc[i2d] + a3 * xc[i3];
        }
    }
    __syncthreads();

    // ---- phase B: GEMM — thread = (o, 8 px) via packed f32x2 FMA ----
    // 512 threads: o = tid & 127, px-quarter q = tid >> 7 (warp-uniform)
    const int o   = tid & 127;
    const int px0 = (tid >> 7) << 3;    // 0, 8, 16, 24

    uint64_t acc[4];
    #pragma unroll
    for (int j = 0; j < 4; j++) acc[j] = 0ull;

    const float* wp = g_wT + o;
    #pragma unroll 4
    for (int r = 0; r < RTOT; r++) {
        float wv = __ldg(wp + (size_t)r * 128);
        uint64_t wv2;
        asm("mov.b64 %0, {%1, %1};" : "=l"(wv2) : "r"(__float_as_uint(wv)));
        const ulonglong2* srow =
            reinterpret_cast<const ulonglong2*>(samp + (size_t)r * TPX + px0);
        ulonglong2 p0 = srow[0];   // px0..px0+3 (LDS.128, warp-uniform -> broadcast)
        ulonglong2 p1 = srow[1];   // px0+4..px0+7
        asm("fma.rn.f32x2 %0, %1, %2, %0;" : "+l"(acc[0]) : "l"(p0.x), "l"(wv2));
        asm("fma.rn.f32x2 %0, %1, %2, %0;" : "+l"(acc[1]) : "l"(p0.y), "l"(wv2));
        asm("fma.rn.f32x2 %0, %1, %2, %0;" : "+l"(acc[2]) : "l"(p1.x), "l"(wv2));
        asm("fma.rn.f32x2 %0, %1, %2, %0;" : "+l"(acc[3]) : "l"(p1.y), "l"(wv2));
    }

    // ---- ReLU + store 8 consecutive floats ----
    float* op = out + ((size_t)b * COUT + o) * HW + h * WDIM + w0 + px0;
    #pragma unroll
    for (int j2 = 0; j2 < 2; j2++) {
        float4 v;
        v.x = fmaxf(__uint_as_float((uint32_t)(acc[2*j2  ]      )), 0.0f);
        v.y = fmaxf(__uint_as_float((uint32_t)(acc[2*j2  ] >> 32)), 0.0f);
        v.z = fmaxf(__uint_as_float((uint32_t)(acc[2*j2+1]      )), 0.0f);
        v.w = fmaxf(__uint_as_float((uint32_t)(acc[2*j2+1] >> 32)), 0.0f);
        reinterpret_cast<float4*>(op)[j2] = v;
    }
}

extern "C" void kernel_launch(void* const* d_in, const int* in_sizes, int n_in,
                              void* d_out, int out_size) {
    const float* x        = (const float*)d_in[0];
    const float* shape    = (const float*)d_in[1];
    const float* w_offset = (const float*)d_in[2];
    const float* w_deform = (const float*)d_in[3];
    float* out = (float*)d_out;

    cudaFuncSetAttribute(deform_kernel,
                         cudaFuncAttributeMaxDynamicSharedMemorySize, SMEM_BYTES);

    prep_wT_kernel<<<(RTOT * COUT + 255) / 256, 256>>>(w_deform);

    const int nblocks = BATCH * HDIM * (WDIM / TPX);   // 2048
    deform_kernel<<<nblocks, NTHREADS, SMEM_BYTES>>>(x, shape, w_offset, out);
}

// round 4
// speedup vs baseline: 2.7241x; 2.7081x over previous
#include <cuda_runtime.h>
#include <cuda_bf16.h>
#include <cstdint>

// ---------------- problem constants ----------------
#define BATCH   4
#define CIN     128
#define COUT    128
#define HDIM    128
#define WDIM    128
#define HW      (HDIM * WDIM)      // 16384
#define NGROUP  4
#define CG      32
#define KTAPS   9
#define RTOT    (CIN * KTAPS)      // 1152 = 18 * 64
#define NCHUNK  18                 // K chunks of 64
#define TPX     32                 // pixels (N) per block
#define NTHREADS 512

// ---------------- smem layout (bytes) ----------------
// S (samples, B operand): hi [1152 k][64 B row, swizzled] = 73728, lo = 73728
// A double buffer: 2 x (hi 16384 | lo 16384) = 65536 @ 147456
// misc @ 212992: ss0(128), ss1(128), swo(576)
#define SMEM_S_OFF   0
#define SMEM_S_LO    73728
#define SMEM_A_OFF   147456
#define SMEM_MISC    212992
#define OFF_SS0      (SMEM_MISC + 0)
#define OFF_SS1      (SMEM_MISC + 128)
#define OFF_SWO      (SMEM_MISC + 256)
#define SMEM_BYTES   (SMEM_MISC + 832)   // 213824

// Pre-swizzled bf16-split weights: 18 chunks x 32768 B (hi 16K | lo 16K), SW128
__device__ __align__(16) int4 g_wA4[NCHUNK * 32768 / 16];

#define SWZ128(b) ((b) ^ (((b) >> 3) & 0x70))

__device__ __forceinline__ uint32_t smem_to_u32(const void* p) {
    uint32_t a;
    asm("{ .reg .u64 t; cvta.to.shared.u64 t, %1; cvt.u32.u64 %0, t; }" : "=r"(a) : "l"(p));
    return a;
}

// S swizzle: row k is 64B (32 px bf16) split into 4 x 16B chunks; chunk index
// XORed with ((k>>1)&3) so the 8 rows ldmatrix touches per phase land on
// disjoint 16B bank groups (even rows use slots {0..3}, odd rows offset 64B).
__device__ __forceinline__ int s_off(int k, int px) {
    return (k << 6) + ((px & 7) << 1) + ((((px >> 3) ^ ((k >> 1) & 3))) << 4);
}

__device__ __forceinline__ void ldsm_x4(uint32_t* r, uint32_t addr) {
    asm volatile("ldmatrix.sync.aligned.m8n8.x4.shared.b16 {%0,%1,%2,%3}, [%4];"
                 : "=r"(r[0]), "=r"(r[1]), "=r"(r[2]), "=r"(r[3]) : "r"(addr));
}
__device__ __forceinline__ void ldsm_x4_trans(uint32_t* r, uint32_t addr) {
    asm volatile("ldmatrix.sync.aligned.m8n8.x4.trans.shared.b16 {%0,%1,%2,%3}, [%4];"
                 : "=r"(r[0]), "=r"(r[1]), "=r"(r[2]), "=r"(r[3]) : "r"(addr));
}
__device__ __forceinline__ void mma_bf16(float* c, const uint32_t* a, uint32_t b0, uint32_t b1) {
    asm volatile(
        "mma.sync.aligned.m16n8k16.row.col.f32.bf16.bf16.f32 "
        "{%0,%1,%2,%3}, {%4,%5,%6,%7}, {%8,%9}, {%0,%1,%2,%3};"
        : "+f"(c[0]), "+f"(c[1]), "+f"(c[2]), "+f"(c[3])
        : "r"(a[0]), "r"(a[1]), "r"(a[2]), "r"(a[3]), "r"(b0), "r"(b1));
}

__device__ __forceinline__ void bf16_split_store(char* hi_p, char* lo_p, float v) {
    __nv_bfloat16 h = __float2bfloat16(v);
    float hf = __bfloat162float(h);
    __nv_bfloat16 l = __float2bfloat16(v - hf);
    *(unsigned short*)hi_p = reinterpret_cast<unsigned short&>(h);
    *(unsigned short*)lo_p = reinterpret_cast<unsigned short&>(l);
}

// ---------------- prep: pre-swizzled bf16-split weight chunks ----------------
// chunk c: [128 o][64 k] bf16, SW128 swizzle, hi plane then lo plane (16KB each)
__global__ void prep_wA_kernel(const float* __restrict__ wd) {
    int idx = blockIdx.x * 256 + threadIdx.x;     // [0, 18*128*64)
    if (idx >= NCHUNK * 128 * 64) return;
    int c   = idx >> 13;
    int rem = idx & 8191;
    int o   = rem >> 6;
    int kk  = rem & 63;
    int r   = c * 64 + kk;
    float w = wd[o * RTOT + r];
    __nv_bfloat16 h = __float2bfloat16(w);
    float hf = __bfloat162float(h);
    __nv_bfloat16 l = __float2bfloat16(w - hf);
    int byte = o * 128 + kk * 2;
    int swz  = SWZ128(byte);
    char* base = (char*)g_wA4 + (size_t)c * 32768;
    *(unsigned short*)(base + swz)         = reinterpret_cast<unsigned short&>(h);
    *(unsigned short*)(base + 16384 + swz) = reinterpret_cast<unsigned short&>(l);
}

// ---------------- main kernel ----------------
__global__ void __launch_bounds__(NTHREADS, 1)
deform_kernel(const float* __restrict__ x,        // [B,C,H,W]
              const float* __restrict__ shape,    // [B,2,H,W]
              const float* __restrict__ w_offset, // [72][2]
              float* __restrict__ out)            // [B,COUT,H,W]
{
    extern __shared__ char smem[];
    const uint32_t smem_u32 = smem_to_u32(smem);
    float* ss0 = (float*)(smem + OFF_SS0);
    float* ss1 = (float*)(smem + OFF_SS1);
    float* swo = (float*)(smem + OFF_SWO);

    const int tid = threadIdx.x;
    const int wid = tid >> 5;
    const int lid = tid & 31;

    const int b   = blockIdx.x >> 9;
    const int rem = blockIdx.x & 511;
    const int h   = rem >> 2;
    const int w0  = (rem & 3) << 5;

    // ---- stage small tables ----
    if (tid < 32)                     ss0[tid]     = shape[(size_t)(b*2+0)*HW + h*WDIM + w0 + tid];
    else if (tid < 64)                ss1[tid-32]  = shape[(size_t)(b*2+1)*HW + h*WDIM + w0 + (tid-32)];
    else if (tid >= 64 && tid < 208)  swo[tid-64]  = w_offset[tid-64];
    __syncthreads();

    // ---- phase A: sample -> bf16 hi/lo into swizzled S [1152][32] ----
    for (int i = tid; i < 36 * TPX; i += NTHREADS) {
        int gk = i >> 5, px = i & 31;
        int g  = gk / 9, k = gk - g * 9;
        int ky = k / 3,  kx = k - ky * 3;
        float s0 = ss0[px], s1 = ss1[px];
        float offy = swo[gk*4 + 0] * s0 + swo[gk*4 + 1] * s1;
        float offx = swo[gk*4 + 2] * s0 + swo[gk*4 + 3] * s1;
        float py  = offy + (float)(ky - 1 + h);
        float pxf = offx + (float)(kx - 1 + w0 + px);
        float y0f = floorf(py), x0f = floorf(pxf);
        float fy = py - y0f, fx = pxf - x0f;
        int y0 = (int)y0f, x0 = (int)x0f;

        float aw[4]; int ai[4];
        #pragma unroll
        for (int t = 0; t < 4; t++) {
            int dy = t >> 1, dx = t & 1;
            int yi = y0 + dy, xi = x0 + dx;
            bool valid = (yi >= 0) && (yi < HDIM) && (xi >= 0) && (xi < WDIM);
            float wy = dy ? fy : 1.0f - fy;
            float wx = dx ? fx : 1.0f - fx;
            int yc = min(max(yi, 0), HDIM - 1);
            int xc = min(max(xi, 0), WDIM - 1);
            aw[t] = valid ? (wy * wx) : 0.0f;
            ai[t] = yc * WDIM + xc;
        }

        const float* xb = x + ((size_t)b * CIN + g * CG) * HW;
        const int r0 = (g * CG) * KTAPS + k;     // r for cg=0; stride 9 per cg
        #pragma unroll 4
        for (int cg = 0; cg < CG; cg++) {
            const float* xc = xb + (size_t)cg * HW;
            float v = aw[0]*xc[ai[0]] + aw[1]*xc[ai[1]] + aw[2]*xc[ai[2]] + aw[3]*xc[ai[3]];
            int r  = r0 + cg * KTAPS;
            int off = s_off(r, px);
            bf16_split_store(smem + SMEM_S_OFF + off, smem + SMEM_S_LO + off, v);
        }
    }

    // ---- copy A chunk 0 (gmem -> smem buf0) ----
    {
        const int4* s = g_wA4;
        int4* d = (int4*)(smem + SMEM_A_OFF);
        #pragma unroll
        for (int j = 0; j < 4; j++) d[tid + j*NTHREADS] = s[tid + j*NTHREADS];
    }
    __syncthreads();

    // ---- phase B: mma.sync GEMM over 18 chunks, A double-buffered ----
    // warp -> o-tile (wid>>1)*16, px half (wid&1)*16
    const int o0 = (wid >> 1) << 4;
    const int n0 = (wid & 1) << 4;

    // A ldmatrix lane address pieces: row = o0 + (lid&15); 16B col sel = lid>>4
    const int arow  = o0 + (lid & 15);
    const int abase = arow * 128;                  // byte offset of row
    const int axor  = (arow & 7) << 4;             // SW128 xor for this row
    const int asel  = (lid >> 4) << 4;             // +16B for k+8 half

    // B ldmatrix lane address pieces: krow = kb + (lid&15); ncol = n0 + ((lid>>4)<<3)
    const int bkrow = lid & 15;
    const int bnchk = (n0 >> 3) + (lid >> 4);      // 16B chunk index of ncol

    float acc[2][4];
    #pragma unroll
    for (int j = 0; j < 2; j++)
        #pragma unroll
        for (int q = 0; q < 4; q++) acc[j][q] = 0.0f;

    for (int c = 0; c < NCHUNK; c++) {
        // prefetch next A chunk into registers
        int4 tmp[4];
        if (c + 1 < NCHUNK) {
            const int4* s = g_wA4 + (size_t)(c + 1) * 2048;
            #pragma unroll
            for (int j = 0; j < 4; j++) tmp[j] = s[tid + j*NTHREADS];
        }

        const uint32_t aplane = smem_u32 + SMEM_A_OFF + ((uint32_t)(c & 1) << 15);
        #pragma unroll
        for (int s4 = 0; s4 < 4; s4++) {
            // ---- A fragments (hi, lo) ----
            int kb_bytes = (s4 << 5) + asel;          // s4*16 elems *2B + half sel
            uint32_t a_addr = aplane + abase + (uint32_t)(kb_bytes ^ axor);
            uint32_t ah[4], al[4];
            ldsm_x4(ah, a_addr);
            ldsm_x4(al, a_addr + 16384);

            // ---- B fragments (hi, lo) ----
            int k = (c << 6) + (s4 << 4) + bkrow;
            int boff = (k << 6) + (((bnchk ^ ((k >> 1) & 3))) << 4);
            uint32_t b_addr = smem_u32 + SMEM_S_OFF + (uint32_t)boff;
            uint32_t bh[4], bl[4];
            ldsm_x4_trans(bh, b_addr);
            ldsm_x4_trans(bl, b_addr + SMEM_S_LO);

            // ---- 3-product split accumulate, 2 n-tiles ----
            mma_bf16(acc[0], ah, bh[0], bh[1]);
            mma_bf16(acc[1], ah, bh[2], bh[3]);
            mma_bf16(acc[0], ah, bl[0], bl[1]);
            mma_bf16(acc[1], ah, bl[2], bl[3]);
            mma_bf16(acc[0], al, bh[0], bh[1]);
            mma_bf16(acc[1], al, bh[2], bh[3]);
        }

        if (c + 1 < NCHUNK) {
            int4* d = (int4*)(smem + SMEM_A_OFF + (((c + 1) & 1) ? 32768u : 0u));
            #pragma unroll
            for (int j = 0; j < 4; j++) d[tid + j*NTHREADS] = tmp[j];
        }
        __syncthreads();
    }

    // ---- epilogue: registers -> ReLU -> gmem ----
    const int g = lid >> 2, t = lid & 3;
    #pragma unroll
    for (int j = 0; j < 2; j++) {
        int px = n0 + (j << 3) + (t << 1);
        float* op0 = out + (((size_t)b * COUT + (o0 + g)) << 14) + (h << 7) + w0 + px;
        float* op1 = op0 + ((size_t)8 << 14);   // row o0+g+8
        float2 v0 = { fmaxf(acc[j][0], 0.0f), fmaxf(acc[j][1], 0.0f) };
        float2 v1 = { fmaxf(acc[j][2], 0.0f), fmaxf(acc[j][3], 0.0f) };
        *reinterpret_cast<float2*>(op0) = v0;
        *reinterpret_cast<float2*>(op1) = v1;
    }
}

extern "C" void kernel_launch(void* const* d_in, const int* in_sizes, int n_in,
                              void* d_out, int out_size) {
    const float* x        = (const float*)d_in[0];
    const float* shape    = (const float*)d_in[1];
    const float* w_offset = (const float*)d_in[2];
    const float* w_deform = (const float*)d_in[3];
    float* out = (float*)d_out;

    cudaFuncSetAttribute(deform_kernel,
                         cudaFuncAttributeMaxDynamicSharedMemorySize, SMEM_BYTES);

    prep_wA_kernel<<<(NCHUNK * 128 * 64 + 255) / 256, 256>>>(w_deform);

    const int nblocks = BATCH * HDIM * (WDIM / TPX);   // 2048
    deform_kernel<<<nblocks, NTHREADS, SMEM_BYTES>>>(x, shape, w_offset, out);
}

// round 5
// speedup vs baseline: 3.5018x; 1.2855x over previous
#include <cuda_runtime.h>
#include <cuda_bf16.h>
#include <cstdint>

// ---------------- problem constants ----------------
#define BATCH   4
#define CIN     128
#define COUT    128
#define HDIM    128
#define WDIM    128
#define HW      (HDIM * WDIM)      // 16384
#define NGROUP  4
#define CG      32
#define KTAPS   9
#define RTOT    (CIN * KTAPS)      // 1152 = 72 * 16
#define NSTEP   72                 // k16 steps
#define TPX     32                 // pixels (N) per block
#define NTHREADS 512

// ---------------- smem layout (bytes) ----------------
// S (samples, B operand): hi [1152 k][64 B swizzled row] = 73728, lo = 73728
// misc @ 147456: ss0(128), ss1(128), swo(576)
#define SMEM_S_OFF   0
#define SMEM_S_LO    73728
#define SMEM_MISC    147456
#define OFF_SS0      (SMEM_MISC + 0)
#define OFF_SS1      (SMEM_MISC + 128)
#define OFF_SWO      (SMEM_MISC + 256)
#define SMEM_BYTES   (SMEM_MISC + 832)   // 148288

// Weights pre-packed in m16n8k16 A-fragment order:
// b32 idx = ((((step*8 + otile)*2 + plane)*32 + lane)*4 + q
//   q=0: row g,   cols t*2,t*2+1   (g=lane>>2, t=lane&3, k-base=step*16)
//   q=1: row g+8, cols t*2,t*2+1
//   q=2: row g,   cols t*2+8,+9
//   q=3: row g+8, cols t*2+8,+9
// plane 0 = bf16 hi, plane 1 = bf16 lo (residual)
__device__ __align__(16) uint32_t g_wAf32[NSTEP * 8 * 2 * 32 * 4];   // 589824 B

__device__ __forceinline__ uint32_t smem_to_u32(const void* p) {
    uint32_t a;
    asm("{ .reg .u64 t; cvta.to.shared.u64 t, %1; cvt.u32.u64 %0, t; }" : "=r"(a) : "l"(p));
    return a;
}

// S swizzle: row k is 64B (32 px bf16), 4 x 16B chunks; chunk XORed with
// ((k>>1)&3) so ldmatrix's 8-row phases hit disjoint 16B groups.
__device__ __forceinline__ int s_off(int k, int px) {
    return (k << 6) + ((px & 7) << 1) + ((((px >> 3) ^ ((k >> 1) & 3))) << 4);
}

__device__ __forceinline__ void ldsm_x4_trans(uint32_t* r, uint32_t addr) {
    asm volatile("ldmatrix.sync.aligned.m8n8.x4.trans.shared.b16 {%0,%1,%2,%3}, [%4];"
                 : "=r"(r[0]), "=r"(r[1]), "=r"(r[2]), "=r"(r[3]) : "r"(addr));
}
__device__ __forceinline__ void mma_bf16(float* c, const uint32_t* a, uint32_t b0, uint32_t b1) {
    asm volatile(
        "mma.sync.aligned.m16n8k16.row.col.f32.bf16.bf16.f32 "
        "{%0,%1,%2,%3}, {%4,%5,%6,%7}, {%8,%9}, {%0,%1,%2,%3};"
        : "+f"(c[0]), "+f"(c[1]), "+f"(c[2]), "+f"(c[3])
        : "r"(a[0]), "r"(a[1]), "r"(a[2]), "r"(a[3]), "r"(b0), "r"(b1));
}

__device__ __forceinline__ void bf16_split_store(char* hi_p, char* lo_p, float v) {
    __nv_bfloat16 h = __float2bfloat16(v);
    float hf = __bfloat162float(h);
    __nv_bfloat16 l = __float2bfloat16(v - hf);
    *(unsigned short*)hi_p = reinterpret_cast<unsigned short&>(h);
    *(unsigned short*)lo_p = reinterpret_cast<unsigned short&>(l);
}

// ---------------- prep: weights -> A-fragment layout, bf16 hi/lo ----------------
__global__ void prep_wAf_kernel(const float* __restrict__ wd) {
    int idx = blockIdx.x * 256 + threadIdx.x;       // b32 index
    if (idx >= NSTEP * 8 * 2 * 32 * 4) return;
    int q     = idx & 3;
    int lane  = (idx >> 2) & 31;
    int plane = (idx >> 7) & 1;
    int ot    = (idx >> 8) & 7;
    int step  = idx >> 11;
    int g = lane >> 2, t = lane & 3;
    int row = ot * 16 + g + ((q & 1) << 3);
    int col = step * 16 + t * 2 + ((q >> 1) << 3);
    float w0 = wd[row * RTOT + col];
    float w1 = wd[row * RTOT + col + 1];
    __nv_bfloat16 h0 = __float2bfloat16(w0);
    __nv_bfloat16 h1 = __float2bfloat16(w1);
    unsigned short u0, u1;
    if (plane == 0) {
        u0 = reinterpret_cast<unsigned short&>(h0);
        u1 = reinterpret_cast<unsigned short&>(h1);
    } else {
        __nv_bfloat16 l0 = __float2bfloat16(w0 - __bfloat162float(h0));
        __nv_bfloat16 l1 = __float2bfloat16(w1 - __bfloat162float(h1));
        u0 = reinterpret_cast<unsigned short&>(l0);
        u1 = reinterpret_cast<unsigned short&>(l1);
    }
    g_wAf32[idx] = ((uint32_t)u1 << 16) | (uint32_t)u0;
}

// ---------------- main kernel ----------------
__global__ void __launch_bounds__(NTHREADS, 1)
deform_kernel(const float* __restrict__ x,        // [B,C,H,W]
              const float* __restrict__ shape,    // [B,2,H,W]
              const float* __restrict__ w_offset, // [72][2]
              float* __restrict__ out)            // [B,COUT,H,W]
{
    extern __shared__ char smem[];
    const uint32_t smem_u32 = smem_to_u32(smem);
    float* ss0 = (float*)(smem + OFF_SS0);
    float* ss1 = (float*)(smem + OFF_SS1);
    float* swo = (float*)(smem + OFF_SWO);

    const int tid = threadIdx.x;
    const int wid = tid >> 5;
    const int lid = tid & 31;

    const int b   = blockIdx.x >> 9;
    const int rem = blockIdx.x & 511;
    const int h   = rem >> 2;
    const int w0  = (rem & 3) << 5;

    // ---- stage small tables ----
    if (tid < 32)                     ss0[tid]     = shape[(size_t)(b*2+0)*HW + h*WDIM + w0 + tid];
    else if (tid < 64)                ss1[tid-32]  = shape[(size_t)(b*2+1)*HW + h*WDIM + w0 + (tid-32)];
    else if (tid >= 64 && tid < 208)  swo[tid-64]  = w_offset[tid-64];
    __syncthreads();

    // ---- phase A: sample -> bf16 hi/lo into swizzled S [1152][32] ----
    for (int i = tid; i < 36 * TPX; i += NTHREADS) {
        int gk = i >> 5, px = i & 31;
        int g  = gk / 9, k = gk - g * 9;
        int ky = k / 3,  kx = k - ky * 3;
        float s0 = ss0[px], s1 = ss1[px];
        float offy = swo[gk*4 + 0] * s0 + swo[gk*4 + 1] * s1;
        float offx = swo[gk*4 + 2] * s0 + swo[gk*4 + 3] * s1;
        float py  = offy + (float)(ky - 1 + h);
        float pxf = offx + (float)(kx - 1 + w0 + px);
        float y0f = floorf(py), x0f = floorf(pxf);
        float fy = py - y0f, fx = pxf - x0f;
        int y0 = (int)y0f, x0 = (int)x0f;

        float aw[4]; int ai[4];
        #pragma unroll
        for (int t = 0; t < 4; t++) {
            int dy = t >> 1, dx = t & 1;
            int yi = y0 + dy, xi = x0 + dx;
            bool valid = (yi >= 0) && (yi < HDIM) && (xi >= 0) && (xi < WDIM);
            float wy = dy ? fy : 1.0f - fy;
            float wx = dx ? fx : 1.0f - fx;
            int yc = min(max(yi, 0), HDIM - 1);
            int xc = min(max(xi, 0), WDIM - 1);
            aw[t] = valid ? (wy * wx) : 0.0f;
            ai[t] = yc * WDIM + xc;
        }

        const float* xb = x + ((size_t)b * CIN + g * CG) * HW;
        const int r0 = (g * CG) * KTAPS + k;     // r for cg=0; stride 9 per cg
        #pragma unroll 4
        for (int cg = 0; cg < CG; cg++) {
            const float* xc = xb + (size_t)cg * HW;
            float v = aw[0]*xc[ai[0]] + aw[1]*xc[ai[1]] + aw[2]*xc[ai[2]] + aw[3]*xc[ai[3]];
            int r  = r0 + cg * KTAPS;
            int off = s_off(r, px);
            bf16_split_store(smem + SMEM_S_OFF + off, smem + SMEM_S_LO + off, v);
        }
    }
    __syncthreads();

    // ---- phase B: 4 GEMM warps (o32 x n32 each); others retire ----
    if (wid >= 4) return;

    const int ot0  = wid << 1;          // otiles {ot0, ot0+1} (o = wid*32 .. +31)
    const int bkrow = lid & 15;
    const int bsel  = lid >> 4;

    const uint4* gA = reinterpret_cast<const uint4*>(g_wAf32);

    float acc[2][4][4];
    #pragma unroll
    for (int a1 = 0; a1 < 2; a1++)
        #pragma unroll
        for (int a2 = 0; a2 < 4; a2++)
            #pragma unroll
            for (int a3 = 0; a3 < 4; a3++) acc[a1][a2][a3] = 0.0f;

    // A fragments: [ot][plane], 16B per lane per (step, otile, plane)
    uint4 curA[2][2];
    #pragma unroll
    for (int ot = 0; ot < 2; ot++)
        #pragma unroll
        for (int pl = 0; pl < 2; pl++)
            curA[ot][pl] = gA[(((0*8 + ot0 + ot)*2 + pl) << 5) + lid];

    for (int step = 0; step < NSTEP; step++) {
        // prefetch next step's A fragments
        uint4 nxtA[2][2];
        if (step + 1 < NSTEP) {
            #pragma unroll
            for (int ot = 0; ot < 2; ot++)
                #pragma unroll
                for (int pl = 0; pl < 2; pl++)
                    nxtA[ot][pl] = gA[((((step+1)*8 + ot0 + ot)*2 + pl) << 5) + lid];
        }

        // B fragments: hi/lo, two n16 halves
        const int k = (step << 4) + bkrow;
        uint32_t bh[2][4], bl[2][4];
        #pragma unroll
        for (int half = 0; half < 2; half++) {
            int bnchk = (half << 1) + bsel;
            int boff  = (k << 6) + (((bnchk ^ ((k >> 1) & 3))) << 4);
            ldsm_x4_trans(bh[half], smem_u32 + SMEM_S_OFF + (uint32_t)boff);
            ldsm_x4_trans(bl[half], smem_u32 + SMEM_S_LO  + (uint32_t)boff);
        }

        // 24 MMAs: (ah*bh + ah*bl + al*bh) x 2 otiles x 4 n8 tiles
        #pragma unroll
        for (int ot = 0; ot < 2; ot++) {
            const uint32_t* ah = (const uint32_t*)&curA[ot][0];
            const uint32_t* al = (const uint32_t*)&curA[ot][1];
            #pragma unroll
            for (int half = 0; half < 2; half++) {
                mma_bf16(acc[ot][half*2+0], ah, bh[half][0], bh[half][1]);
                mma_bf16(acc[ot][half*2+1], ah, bh[half][2], bh[half][3]);
                mma_bf16(acc[ot][half*2+0], ah, bl[half][0], bl[half][1]);
                mma_bf16(acc[ot][half*2+1], ah, bl[half][2], bl[half][3]);
                mma_bf16(acc[ot][half*2+0], al, bh[half][0], bh[half][1]);
                mma_bf16(acc[ot][half*2+1], al, bh[half][2], bh[half][3]);
            }
        }

        #pragma unroll
        for (int ot = 0; ot < 2; ot++)
            #pragma unroll
            for (int pl = 0; pl < 2; pl++)
                curA[ot][pl] = nxtA[ot][pl];
    }

    // ---- epilogue: acc -> ReLU -> gmem ----
    const int g = lid >> 2, t = lid & 3;
    #pragma unroll
    for (int ot = 0; ot < 2; ot++) {
        #pragma unroll
        for (int j = 0; j < 4; j++) {
            int o  = (wid << 5) + (ot << 4) + g;
            int px = (j << 3) + (t << 1);
            float* op0 = out + (((size_t)b * COUT + o) << 14) + (h << 7) + w0 + px;
            float* op1 = op0 + ((size_t)8 << 14);   // row o+8
            float2 v0 = { fmaxf(acc[ot][j][0], 0.0f), fmaxf(acc[ot][j][1], 0.0f) };
            float2 v1 = { fmaxf(acc[ot][j][2], 0.0f), fmaxf(acc[ot][j][3], 0.0f) };
            *reinterpret_cast<float2*>(op0) = v0;
            *reinterpret_cast<float2*>(op1) = v1;
        }
    }
}

extern "C" void kernel_launch(void* const* d_in, const int* in_sizes, int n_in,
                              void* d_out, int out_size) {
    const float* x        = (const float*)d_in[0];
    const float* shape    = (const float*)d_in[1];
    const float* w_offset = (const float*)d_in[2];
    const float* w_deform = (const float*)d_in[3];
    float* out = (float*)d_out;

    cudaFuncSetAttribute(deform_kernel,
                         cudaFuncAttributeMaxDynamicSharedMemorySize, SMEM_BYTES);

    prep_wAf_kernel<<<(NSTEP * 8 * 2 * 32 * 4 + 255) / 256, 256>>>(w_deform);

    const int nblocks = BATCH * HDIM * (WDIM / TPX);   // 2048
    deform_kernel<<<nblocks, NTHREADS, SMEM_BYTES>>>(x, shape, w_offset, out);
}

// round 6
// speedup vs baseline: 3.7048x; 1.0580x over previous
#include <cuda_runtime.h>
#include <cuda_bf16.h>
#include <cstdint>

// ---------------- problem constants ----------------
#define BATCH   4
#define CIN     128
#define COUT    128
#define HDIM    128
#define WDIM    128
#define HW      (HDIM * WDIM)      // 16384
#define NGROUP  4
#define CG      32
#define KTAPS   9
#define RTOT    (CIN * KTAPS)      // 1152 = 72 * 16
#define NSTEP   72                 // k16 steps
#define TPX     16                 // pixels (N) per block
#define NTHREADS 256

// ---------------- smem layout (bytes) ----------------
// S: hi [1152 k][32 B swizzled row] = 36864, lo = 36864
// misc @ 73728: ss0(64), ss1(64), swo(576)
#define SMEM_S_OFF   0
#define SMEM_S_LO    36864
#define SMEM_MISC    73728
#define OFF_SS0      (SMEM_MISC + 0)
#define OFF_SS1      (SMEM_MISC + 64)
#define OFF_SWO      (SMEM_MISC + 128)
#define SMEM_BYTES   (SMEM_MISC + 704)   // 74432

// Weights pre-packed in m16n8k16 A-fragment order:
// b32 idx = ((((step*8 + otile)*2 + plane)*32 + lane)*4 + q
//   plane 0 = bf16 hi, plane 1 = bf16 lo (residual)
__device__ __align__(16) uint32_t g_wAf32[NSTEP * 8 * 2 * 32 * 4];   // 589824 B

__device__ __forceinline__ uint32_t smem_to_u32(const void* p) {
    uint32_t a;
    asm("{ .reg .u64 t; cvta.to.shared.u64 t, %1; cvt.u32.u64 %0, t; }" : "=r"(a) : "l"(p));
    return a;
}

// S swizzle for 32B rows: 2 x 16B chunks; chunk (px>>3) XOR ((k>>2)&1).
// ldmatrix phase (8 rows x 16B) then hits 8 distinct 16B slots mod 128B.
__device__ __forceinline__ int s_off(int k, int px) {
    return (k << 5) + ((px & 7) << 1) + ((((px >> 3) ^ ((k >> 2) & 1))) << 4);
}

__device__ __forceinline__ void ldsm_x4_trans(uint32_t* r, uint32_t addr) {
    asm volatile("ldmatrix.sync.aligned.m8n8.x4.trans.shared.b16 {%0,%1,%2,%3}, [%4];"
                 : "=r"(r[0]), "=r"(r[1]), "=r"(r[2]), "=r"(r[3]) : "r"(addr));
}
__device__ __forceinline__ void mma_bf16(float* c, const uint32_t* a, uint32_t b0, uint32_t b1) {
    asm volatile(
        "mma.sync.aligned.m16n8k16.row.col.f32.bf16.bf16.f32 "
        "{%0,%1,%2,%3}, {%4,%5,%6,%7}, {%8,%9}, {%0,%1,%2,%3};"
        : "+f"(c[0]), "+f"(c[1]), "+f"(c[2]), "+f"(c[3])
        : "r"(a[0]), "r"(a[1]), "r"(a[2]), "r"(a[3]), "r"(b0), "r"(b1));
}

__device__ __forceinline__ void bf16_split_store(char* hi_p, char* lo_p, float v) {
    __nv_bfloat16 h = __float2bfloat16(v);
    float hf = __bfloat162float(h);
    __nv_bfloat16 l = __float2bfloat16(v - hf);
    *(unsigned short*)hi_p = reinterpret_cast<unsigned short&>(h);
    *(unsigned short*)lo_p = reinterpret_cast<unsigned short&>(l);
}

// ---------------- prep: weights -> A-fragment layout, bf16 hi/lo ----------------
__global__ void prep_wAf_kernel(const float* __restrict__ wd) {
    int idx = blockIdx.x * 256 + threadIdx.x;       // b32 index
    if (idx >= NSTEP * 8 * 2 * 32 * 4) return;
    int q     = idx & 3;
    int lane  = (idx >> 2) & 31;
    int plane = (idx >> 7) & 1;
    int ot    = (idx >> 8) & 7;
    int step  = idx >> 11;
    int g = lane >> 2, t = lane & 3;
    int row = ot * 16 + g + ((q & 1) << 3);
    int col = step * 16 + t * 2 + ((q >> 1) << 3);
    float w0 = wd[row * RTOT + col];
    float w1 = wd[row * RTOT + col + 1];
    __nv_bfloat16 h0 = __float2bfloat16(w0);
    __nv_bfloat16 h1 = __float2bfloat16(w1);
    unsigned short u0, u1;
    if (plane == 0) {
        u0 = reinterpret_cast<unsigned short&>(h0);
        u1 = reinterpret_cast<unsigned short&>(h1);
    } else {
        __nv_bfloat16 l0 = __float2bfloat16(w0 - __bfloat162float(h0));
        __nv_bfloat16 l1 = __float2bfloat16(w1 - __bfloat162float(h1));
        u0 = reinterpret_cast<unsigned short&>(l0);
        u1 = reinterpret_cast<unsigned short&>(l1);
    }
    g_wAf32[idx] = ((uint32_t)u1 << 16) | (uint32_t)u0;
}

// ---------------- main kernel ----------------
__global__ void __launch_bounds__(NTHREADS, 2)
deform_kernel(const float* __restrict__ x,        // [B,C,H,W]
              const float* __restrict__ shape,    // [B,2,H,W]
              const float* __restrict__ w_offset, // [72][2]
              float* __restrict__ out)            // [B,COUT,H,W]
{
    extern __shared__ char smem[];
    const uint32_t smem_u32 = smem_to_u32(smem);
    float* ss0 = (float*)(smem + OFF_SS0);
    float* ss1 = (float*)(smem + OFF_SS1);
    float* swo = (float*)(smem + OFF_SWO);

    const int tid = threadIdx.x;
    const int wid = tid >> 5;
    const int lid = tid & 31;

    // 1024 pixel tiles per batch image: h in [0,128), w tile in [0,8)
    const int b   = blockIdx.x >> 10;
    const int rem = blockIdx.x & 1023;
    const int h   = rem >> 3;
    const int w0  = (rem & 7) << 4;

    // ---- stage small tables ----
    if (tid < 16)                     ss0[tid]     = shape[(size_t)(b*2+0)*HW + h*WDIM + w0 + tid];
    else if (tid < 32)                ss1[tid-16]  = shape[(size_t)(b*2+1)*HW + h*WDIM + w0 + (tid-16)];
    else if (tid >= 32 && tid < 176)  swo[tid-32]  = w_offset[tid-32];
    __syncthreads();

    // ---- phase A: sample -> bf16 hi/lo into swizzled S [1152][16] ----
    for (int i = tid; i < 36 * TPX; i += NTHREADS) {
        int gk = i >> 4, px = i & 15;
        int g  = gk / 9, k = gk - g * 9;
        int ky = k / 3,  kx = k - ky * 3;
        float s0 = ss0[px], s1 = ss1[px];
        float offy = swo[gk*4 + 0] * s0 + swo[gk*4 + 1] * s1;
        float offx = swo[gk*4 + 2] * s0 + swo[gk*4 + 3] * s1;
        float py  = offy + (float)(ky - 1 + h);
        float pxf = offx + (float)(kx - 1 + w0 + px);
        float y0f = floorf(py), x0f = floorf(pxf);
        float fy = py - y0f, fx = pxf - x0f;
        int y0 = (int)y0f, x0 = (int)x0f;

        float aw[4]; int ai[4];
        #pragma unroll
        for (int t = 0; t < 4; t++) {
            int dy = t >> 1, dx = t & 1;
            int yi = y0 + dy, xi = x0 + dx;
            bool valid = (yi >= 0) && (yi < HDIM) && (xi >= 0) && (xi < WDIM);
            float wy = dy ? fy : 1.0f - fy;
            float wx = dx ? fx : 1.0f - fx;
            int yc = min(max(yi, 0), HDIM - 1);
            int xc = min(max(xi, 0), WDIM - 1);
            aw[t] = valid ? (wy * wx) : 0.0f;
            ai[t] = yc * WDIM + xc;
        }

        const float* xb = x + ((size_t)b * CIN + g * CG) * HW;
        const int r0 = (g * CG) * KTAPS + k;     // r for cg=0; stride 9 per cg
        #pragma unroll 4
        for (int cg = 0; cg < CG; cg++) {
            const float* xc = xb + (size_t)cg * HW;
            float v = aw[0]*xc[ai[0]] + aw[1]*xc[ai[1]] + aw[2]*xc[ai[2]] + aw[3]*xc[ai[3]];
            int r  = r0 + cg * KTAPS;
            int off = s_off(r, px);
            bf16_split_store(smem + SMEM_S_OFF + off, smem + SMEM_S_LO + off, v);
        }
    }
    __syncthreads();

    // ---- phase B: 4 GEMM warps (o32 x n16 each); warps 4-7 retire ----
    if (wid >= 4) return;

    const int ot0   = wid << 1;          // otiles {ot0, ot0+1}
    const int bkrow = lid & 15;
    const int bsel  = lid >> 4;          // 16B chunk (8 px)

    const uint4* gA = reinterpret_cast<const uint4*>(g_wAf32);

    float acc[2][2][4];
    #pragma unroll
    for (int a1 = 0; a1 < 2; a1++)
        #pragma unroll
        for (int a2 = 0; a2 < 2; a2++)
            #pragma unroll
            for (int a3 = 0; a3 < 4; a3++) acc[a1][a2][a3] = 0.0f;

    // A fragments: [ot][plane], 16B per lane per (step, otile, plane)
    uint4 curA[2][2];
    #pragma unroll
    for (int ot = 0; ot < 2; ot++)
        #pragma unroll
        for (int pl = 0; pl < 2; pl++)
            curA[ot][pl] = gA[(((0*8 + ot0 + ot)*2 + pl) << 5) + lid];

    for (int step = 0; step < NSTEP; step++) {
        // prefetch next step's A fragments (L2-resident stream)
        uint4 nxtA[2][2];
        if (step + 1 < NSTEP) {
            #pragma unroll
            for (int ot = 0; ot < 2; ot++)
                #pragma unroll
                for (int pl = 0; pl < 2; pl++)
                    nxtA[ot][pl] = gA[((((step+1)*8 + ot0 + ot)*2 + pl) << 5) + lid];
        }

        // B fragments: hi/lo planes, full n16
        const int k = (step << 4) + bkrow;
        const int boff = (k << 5) + (((bsel ^ ((k >> 2) & 1))) << 4);
        uint32_t bh[4], bl[4];
        ldsm_x4_trans(bh, smem_u32 + SMEM_S_OFF + (uint32_t)boff);
        ldsm_x4_trans(bl, smem_u32 + SMEM_S_LO  + (uint32_t)boff);

        // 12 MMAs: (ah*bh + ah*bl + al*bh) x 2 otiles x 2 n8 tiles
        #pragma unroll
        for (int ot = 0; ot < 2; ot++) {
            const uint32_t* ah = (const uint32_t*)&curA[ot][0];
            const uint32_t* al = (const uint32_t*)&curA[ot][1];
            mma_bf16(acc[ot][0], ah, bh[0], bh[1]);
            mma_bf16(acc[ot][1], ah, bh[2], bh[3]);
            mma_bf16(acc[ot][0], ah, bl[0], bl[1]);
            mma_bf16(acc[ot][1], ah, bl[2], bl[3]);
            mma_bf16(acc[ot][0], al, bh[0], bh[1]);
            mma_bf16(acc[ot][1], al, bh[2], bh[3]);
        }

        #pragma unroll
        for (int ot = 0; ot < 2; ot++)
            #pragma unroll
            for (int pl = 0; pl < 2; pl++)
                curA[ot][pl] = nxtA[ot][pl];
    }

    // ---- epilogue: acc -> ReLU -> gmem ----
    const int g = lid >> 2, t = lid & 3;
    #pragma unroll
    for (int ot = 0; ot < 2; ot++) {
        #pragma unroll
        for (int j = 0; j < 2; j++) {
            int o  = (wid << 5) + (ot << 4) + g;
            int px = (j << 3) + (t << 1);
            float* op0 = out + (((size_t)b * COUT + o) << 14) + (h << 7) + w0 + px;
            float* op1 = op0 + ((size_t)8 << 14);   // row o+8
            float2 v0 = { fmaxf(acc[ot][j][0], 0.0f), fmaxf(acc[ot][j][1], 0.0f) };
            float2 v1 = { fmaxf(acc[ot][j][2], 0.0f), fmaxf(acc[ot][j][3], 0.0f) };
            *reinterpret_cast<float2*>(op0) = v0;
            *reinterpret_cast<float2*>(op1) = v1;
        }
    }
}

extern "C" void kernel_launch(void* const* d_in, const int* in_sizes, int n_in,
                              void* d_out, int out_size) {
    const float* x        = (const float*)d_in[0];
    const float* shape    = (const float*)d_in[1];
    const float* w_offset = (const float*)d_in[2];
    const float* w_deform = (const float*)d_in[3];
    float* out = (float*)d_out;

    cudaFuncSetAttribute(deform_kernel,
                         cudaFuncAttributeMaxDynamicSharedMemorySize, SMEM_BYTES);

    prep_wAf_kernel<<<(NSTEP * 8 * 2 * 32 * 4 + 255) / 256, 256>>>(w_deform);

    const int nblocks = BATCH * HDIM * (WDIM / TPX);   // 4096
    deform_kernel<<<nblocks, NTHREADS, SMEM_BYTES>>>(x, shape, w_offset, out);
}